// round 14
// baseline (speedup 1.0000x reference)
#include <cuda_runtime.h>

// Problem constants (fixed by the reference)
#define SEQ_LEN   512
#define EMB       768
#define NLAB      9
#define FEAT      2354            // 3*768 + 50
#define WDIM      50
#define MAXW      16
#define NSPANS    32768
#define HALFK     384             // EMB/2 per k-half warp-group
#define HALF_OUT  (NSPANS * NLAB / 2)   // 147456

// Packed fp32x2 FMA (Blackwell FFMA2 — only reachable via PTX f32x2)
#define FMA_F32X2(d, a, b, c) \
    asm("fma.rn.f32x2 %0, %1, %2, %3;" : "=l"(d) : "l"(a), "l"(b), "l"(c))

// Packed tables (allocation-free rule: __device__ globals)
// g_S[t*9+l] = (Ps[t][l], Pc[t][l])   Pc = exclusive prefix of Pa
// g_E[t*9+l] = (Pe[t][l], Pc[t][l])
// g_Wb[w*9+l] = (width_proj + bias, 1/w)
__device__ float2 g_S[SEQ_LEN * NLAB];
__device__ float2 g_E[SEQ_LEN * NLAB];
__device__ float  g_Pa[SEQ_LEN * NLAB];
__device__ float2 g_Wb[(MAXW + 1) * NLAB];

// ---------------------------------------------------------------------------
// K1: token projection — R13's measured-best body (explicit scalar
// accumulators -> 56 regs, high MLP; 6.85us). 256 blocks x 576 threads,
// 2 tokens/block, k-split across 2 warp-groups, packed f32x2 FMAs.
// PDL trigger releases K2 at store time.
// ---------------------------------------------------------------------------
__global__ void __launch_bounds__(576)
proj_kernel(const float* __restrict__ seq, const float* __restrict__ W) {
    __shared__ __align__(16) float srow[2][EMB];      // 6 KB
    __shared__ float spart[2][2 * 27];                // [token][kh*27+j]

    const int tid  = threadIdx.x;
    const int warp = tid >> 5;          // 0..17
    const int lane = tid & 31;
    const int t0   = blockIdx.x * 2;

    // Stage both token rows (384 float4 total).
    if (tid < 2 * EMB / 4) {
        const float4 v = reinterpret_cast<const float4*>(seq + (size_t)t0 * EMB)[tid];
        reinterpret_cast<float4*>(&srow[0][0])[tid] = v;
    }
    __syncthreads();

    const int kh    = warp / 9;         // 0..1  k-half
    const int jg    = warp - 9 * kh;    // 0..8  dot-group
    const int kbase = kh * HALFK;

    const float* wbase[3];
    #pragma unroll
    for (int i = 0; i < 3; i++) {
        const int j = jg * 3 + i;
        const int l = j % 9, sl = j / 9;
        wbase[i] = W + (size_t)l * FEAT + sl * EMB + kbase;   // 8B-aligned
    }

    unsigned long long a0[3] = {0ull, 0ull, 0ull};
    unsigned long long a1[3] = {0ull, 0ull, 0ull};

    #pragma unroll
    for (int it = 0; it < 6; it++) {
        const int k = it * 64 + lane * 2;
        const unsigned long long s0 =
            *reinterpret_cast<const unsigned long long*>(&srow[0][kbase + k]);
        const unsigned long long s1 =
            *reinterpret_cast<const unsigned long long*>(&srow[1][kbase + k]);
        #pragma unroll
        for (int i = 0; i < 3; i++) {
            const unsigned long long wv =
                __ldg(reinterpret_cast<const unsigned long long*>(wbase[i] + k));
            FMA_F32X2(a0[i], s0, wv, a0[i]);
            FMA_F32X2(a1[i], s1, wv, a1[i]);
        }
    }

    // Collapse f32x2 -> f32, shfl-reduce across lanes.
    float r0[3], r1[3];
    #pragma unroll
    for (int i = 0; i < 3; i++) {
        const float2 f0 = *reinterpret_cast<float2*>(&a0[i]);
        const float2 f1 = *reinterpret_cast<float2*>(&a1[i]);
        r0[i] = f0.x + f0.y;
        r1[i] = f1.x + f1.y;
    }
    #pragma unroll
    for (int i = 0; i < 3; i++) {
        #pragma unroll
        for (int o = 16; o > 0; o >>= 1) {
            r0[i] += __shfl_down_sync(0xffffffffu, r0[i], o);
            r1[i] += __shfl_down_sync(0xffffffffu, r1[i], o);
        }
    }
    if (lane == 0) {
        #pragma unroll
        for (int i = 0; i < 3; i++) {
            spart[0][kh * 27 + jg * 3 + i] = r0[i];
            spart[1][kh * 27 + jg * 3 + i] = r1[i];
        }
    }
    __syncthreads();

    // Combine the two k-halves; 54 threads write finals.
    if (tid < 54) {
        const int t = tid / 27;             // 0..1
        const int j = tid - t * 27;         // 0..26
        const float v = spart[t][j] + spart[t][27 + j];
        const int sl = j / 9, l = j - sl * 9;
        const int tok = t0 + t;
        if (sl == 0)
            reinterpret_cast<float*>(g_S)[(tok * NLAB + l) * 2] = v;
        else if (sl == 1)
            reinterpret_cast<float*>(g_E)[(tok * NLAB + l) * 2] = v;
        else
            g_Pa[tok * NLAB + l] = v;
    }
    __syncthreads();
    cudaTriggerProgrammaticLaunchCompletion();   // release K2 at last-store time
}

// ---------------------------------------------------------------------------
// K2 (PDL): width-table prologue (inputs only, overlaps K1) -> HW grid sync
// -> 9 parallel scans over 512 tokens (one block, 512 threads).
// ---------------------------------------------------------------------------
__global__ void __launch_bounds__(512)
scan_kernel(const float* __restrict__ wt,
            const float* __restrict__ W,
            const float* __restrict__ b) {
    __shared__ float tot[16][NLAB];
    __shared__ float carry[16][NLAB];

    const int tid  = threadIdx.x;
    const int lane = tid & 31;
    const int warp = tid >> 5;

    if (tid < (MAXW + 1) * NLAB) {
        const int w = tid / NLAB;
        const int l = tid % NLAB;
        const float* wrow = W + (size_t)l * FEAT + 3 * EMB;
        float a = __ldg(b + l);
        #pragma unroll
        for (int k = 0; k < WDIM; k++)
            a += __ldg(wt + w * WDIM + k) * __ldg(wrow + k);
        g_Wb[tid] = make_float2(a, 1.0f / (float)w);   // w=0 never read
    }

    cudaGridDependencySynchronize();      // HW wait for K1 (no polling, no fence)

    float x[NLAB], a[NLAB];
    #pragma unroll
    for (int l = 0; l < NLAB; l++) { x[l] = g_Pa[tid * NLAB + l]; a[l] = x[l]; }

    #pragma unroll
    for (int l = 0; l < NLAB; l++) {
        #pragma unroll
        for (int o = 1; o < 32; o <<= 1) {
            const float y = __shfl_up_sync(0xffffffffu, a[l], o);
            if (lane >= o) a[l] += y;
        }
    }
    if (lane == 31) {
        #pragma unroll
        for (int l = 0; l < NLAB; l++) tot[warp][l] = a[l];
    }
    __syncthreads();
    if (tid < NLAB) {
        float r = 0.f;
        #pragma unroll
        for (int w = 0; w < 16; w++) { carry[w][tid] = r; r += tot[w][tid]; }
    }
    __syncthreads();
    #pragma unroll
    for (int l = 0; l < NLAB; l++) {
        const float excl = a[l] - x[l] + carry[warp][l];   // Pc[tid]
        reinterpret_cast<float*>(g_S)[(tid * NLAB + l) * 2 + 1] = excl;
        reinterpret_cast<float*>(g_E)[(tid * NLAB + l) * 2 + 1] = excl;
    }
    __syncthreads();
    cudaTriggerProgrammaticLaunchCompletion();   // release K3 at last-store time
}

// ---------------------------------------------------------------------------
// K3 (PDL): assemble, 2 elements/thread at full grid width.
// 512 blocks x 288 thr; thread handles m and m+147456. All 6 idx loads
// issue before the 6 dependent table loads (2x MLP on the idx->table chain)
// while occupancy stays high. Coalesced stores in both halves.
// ---------------------------------------------------------------------------
__global__ void __launch_bounds__(288)
assemble_kernel(const int* __restrict__ st,
                const int* __restrict__ en,
                const int* __restrict__ wd,
                float* __restrict__ out) {
    const int tid  = threadIdx.x;
    const int sp_l = tid / NLAB;                 // 0..31
    const int l    = tid - sp_l * NLAB;          // 0..8
    const int spanA = blockIdx.x * 32 + sp_l;            // first half
    const int spanB = spanA + NSPANS / 2;                // second half

    // prologue: inputs only (overlaps K2 via PDL)
    const int sA = __ldg(st + spanA);
    const int eA = __ldg(en + spanA);
    const int wA = __ldg(wd + spanA);
    const int sB = __ldg(st + spanB);
    const int eB = __ldg(en + spanB);
    const int wB = __ldg(wd + spanB);
    const int isA = sA * NLAB + l, ieA = eA * NLAB + l, iwA = wA * NLAB + l;
    const int isB = sB * NLAB + l, ieB = eB * NLAB + l, iwB = wB * NLAB + l;

    cudaGridDependencySynchronize();             // HW wait for K2

    const float2 fsA = __ldg(&g_S[isA]);
    const float2 feA = __ldg(&g_E[ieA]);
    const float2 fwA = __ldg(&g_Wb[iwA]);
    const float2 fsB = __ldg(&g_S[isB]);
    const float2 feB = __ldg(&g_E[ieB]);
    const float2 fwB = __ldg(&g_Wb[iwB]);

    const int m = blockIdx.x * 288 + tid;
    out[m]            = fsA.x + feA.x + (feA.y - fsA.y) * fwA.y + fwA.x;
    out[m + HALF_OUT] = fsB.x + feB.x + (feB.y - fsB.y) * fwB.y + fwB.x;
}

// ---------------------------------------------------------------------------
extern "C" void kernel_launch(void* const* d_in, const int* in_sizes, int n_in,
                              void* d_out, int out_size) {
    const float* seq = (const float*)d_in[0];   // [1,512,768]
    const int*   st  = (const int*)  d_in[1];   // [32768]
    const int*   en  = (const int*)  d_in[2];   // [32768]
    const int*   wd  = (const int*)  d_in[3];   // [32768]
    const float* wt  = (const float*)d_in[4];   // [17,50]
    const float* W   = (const float*)d_in[5];   // [9,2354]
    const float* b   = (const float*)d_in[6];   // [9]
    float* out = (float*)d_out;                 // [32768,9]

    proj_kernel<<<SEQ_LEN / 2, 576>>>(seq, W);

    cudaLaunchAttribute at[1];
    at[0].id = cudaLaunchAttributeProgrammaticStreamSerialization;
    at[0].val.programmaticStreamSerializationAllowed = 1;

    {   // K2 with PDL
        cudaLaunchConfig_t cfg = {};
        cfg.gridDim = dim3(1, 1, 1);
        cfg.blockDim = dim3(512, 1, 1);
        cfg.stream = 0;
        cfg.attrs = at;
        cfg.numAttrs = 1;
        cudaLaunchKernelEx(&cfg, scan_kernel, wt, W, b);
    }
    {   // K3 with PDL
        cudaLaunchConfig_t cfg = {};
        cfg.gridDim = dim3(NSPANS / 64, 1, 1);   // 512 blocks
        cfg.blockDim = dim3(288, 1, 1);
        cfg.stream = 0;
        cfg.attrs = at;
        cfg.numAttrs = 1;
        cudaLaunchKernelEx(&cfg, assemble_kernel, st, en, wd, out);
    }
}

// round 15
// speedup vs baseline: 1.1165x; 1.1165x over previous
#include <cuda_runtime.h>

// Problem constants (fixed by the reference)
#define SEQ_LEN   512
#define EMB       768
#define NLAB      9
#define FEAT      2354            // 3*768 + 50
#define WDIM      50
#define MAXW      16
#define NSPANS    32768
#define HALFK     384             // EMB/2 per k-half warp-group

// Packed fp32x2 FMA (Blackwell FFMA2 — only reachable via PTX f32x2)
#define FMA_F32X2(d, a, b, c) \
    asm("fma.rn.f32x2 %0, %1, %2, %3;" : "=l"(d) : "l"(a), "l"(b), "l"(c))

// Tables (allocation-free rule: __device__ globals)
__device__ float  g_Ps[SEQ_LEN * NLAB];      // start-token projection
__device__ float  g_Pe[SEQ_LEN * NLAB];      // end-token projection
__device__ float4 g_Pa4[SEQ_LEN * NLAB / 4]; // avg-slice projection (16B-aligned)

// ---------------------------------------------------------------------------
// K1: token projection — R13's measured-best body (explicit scalar
// accumulators -> 56 regs, high MLP; 6.85us). 256 blocks x 576 threads,
// 2 tokens/block, k-split across 2 warp-groups, packed f32x2 FMAs.
// PDL trigger releases K2 at store time.
// ---------------------------------------------------------------------------
__global__ void __launch_bounds__(576)
proj_kernel(const float* __restrict__ seq, const float* __restrict__ W) {
    __shared__ __align__(16) float srow[2][EMB];      // 6 KB
    __shared__ float spart[2][2 * 27];                // [token][kh*27+j]

    const int tid  = threadIdx.x;
    const int warp = tid >> 5;          // 0..17
    const int lane = tid & 31;
    const int t0   = blockIdx.x * 2;

    // Stage both token rows (384 float4 total).
    if (tid < 2 * EMB / 4) {
        const float4 v = reinterpret_cast<const float4*>(seq + (size_t)t0 * EMB)[tid];
        reinterpret_cast<float4*>(&srow[0][0])[tid] = v;
    }
    __syncthreads();

    const int kh    = warp / 9;         // 0..1  k-half
    const int jg    = warp - 9 * kh;    // 0..8  dot-group
    const int kbase = kh * HALFK;

    const float* wbase[3];
    #pragma unroll
    for (int i = 0; i < 3; i++) {
        const int j = jg * 3 + i;
        const int l = j % 9, sl = j / 9;
        wbase[i] = W + (size_t)l * FEAT + sl * EMB + kbase;   // 8B-aligned
    }

    unsigned long long a0[3] = {0ull, 0ull, 0ull};
    unsigned long long a1[3] = {0ull, 0ull, 0ull};

    #pragma unroll
    for (int it = 0; it < 6; it++) {
        const int k = it * 64 + lane * 2;
        const unsigned long long s0 =
            *reinterpret_cast<const unsigned long long*>(&srow[0][kbase + k]);
        const unsigned long long s1 =
            *reinterpret_cast<const unsigned long long*>(&srow[1][kbase + k]);
        #pragma unroll
        for (int i = 0; i < 3; i++) {
            const unsigned long long wv =
                __ldg(reinterpret_cast<const unsigned long long*>(wbase[i] + k));
            FMA_F32X2(a0[i], s0, wv, a0[i]);
            FMA_F32X2(a1[i], s1, wv, a1[i]);
        }
    }

    // Collapse f32x2 -> f32, shfl-reduce across lanes.
    float r0[3], r1[3];
    #pragma unroll
    for (int i = 0; i < 3; i++) {
        const float2 f0 = *reinterpret_cast<float2*>(&a0[i]);
        const float2 f1 = *reinterpret_cast<float2*>(&a1[i]);
        r0[i] = f0.x + f0.y;
        r1[i] = f1.x + f1.y;
    }
    #pragma unroll
    for (int i = 0; i < 3; i++) {
        #pragma unroll
        for (int o = 16; o > 0; o >>= 1) {
            r0[i] += __shfl_down_sync(0xffffffffu, r0[i], o);
            r1[i] += __shfl_down_sync(0xffffffffu, r1[i], o);
        }
    }
    if (lane == 0) {
        #pragma unroll
        for (int i = 0; i < 3; i++) {
            spart[0][kh * 27 + jg * 3 + i] = r0[i];
            spart[1][kh * 27 + jg * 3 + i] = r1[i];
        }
    }
    __syncthreads();

    // Combine the two k-halves; 54 threads write finals.
    if (tid < 54) {
        const int t = tid / 27;             // 0..1
        const int j = tid - t * 27;         // 0..26
        const float v = spart[t][j] + spart[t][27 + j];
        const int sl = j / 9, l = j - sl * 9;
        const int tok = t0 + t;
        if (sl == 0)      g_Ps[tok * NLAB + l] = v;
        else if (sl == 1) g_Pe[tok * NLAB + l] = v;
        else              reinterpret_cast<float*>(g_Pa4)[tok * NLAB + l] = v;
    }
    __syncthreads();
    cudaTriggerProgrammaticLaunchCompletion();   // release K2 at last-store time
}

// ---------------------------------------------------------------------------
// K2 (PDL): scan + assemble fused. 512 blocks x 288 thr (32 spans x 9 labels,
// 2 span-halves per thread).
//  prologue (inputs only, overlaps proj): idx loads + width table -> smem
//  gridsync(proj) -> coalesced load of g_Pa (18 KB) -> redundant in-block
//  9-label scan (threads 0..255, 2 tokens each) -> Pc in smem -> assemble.
// One kernel hop removed vs the 3-kernel pipeline.
// ---------------------------------------------------------------------------
__global__ void __launch_bounds__(288)
assemble_kernel(const int* __restrict__ st,
                const int* __restrict__ en,
                const int* __restrict__ wd,
                const float* __restrict__ wt,
                const float* __restrict__ W,
                const float* __restrict__ b,
                float* __restrict__ out) {
    __shared__ __align__(16) float sPc[SEQ_LEN * NLAB];  // Pa, scanned in place
    __shared__ float2 sWb[(MAXW + 1) * NLAB];
    __shared__ float tot[8][NLAB];
    __shared__ float carry[8][NLAB];

    const int tid  = threadIdx.x;
    const int lane = tid & 31;
    const int warp = tid >> 5;
    const int sp_l = tid / NLAB;                 // 0..31
    const int l    = tid - sp_l * NLAB;          // 0..8
    const int spanA = blockIdx.x * 32 + sp_l;
    const int spanB = spanA + NSPANS / 2;

    // ---- prologue: inputs only (overlaps proj via PDL) ----
    const int sA = __ldg(st + spanA);
    const int eA = __ldg(en + spanA);
    const int wA = __ldg(wd + spanA);
    const int sB = __ldg(st + spanB);
    const int eB = __ldg(en + spanB);
    const int wB = __ldg(wd + spanB);

    if (tid < (MAXW + 1) * NLAB) {
        const int w = tid / NLAB;
        const int ll = tid - w * NLAB;
        const float* wrow = W + (size_t)ll * FEAT + 3 * EMB;
        float a = __ldg(b + ll);
        #pragma unroll
        for (int k = 0; k < WDIM; k++)
            a += __ldg(wt + w * WDIM + k) * __ldg(wrow + k);
        sWb[tid] = make_float2(a, 1.0f / (float)w);   // w=0 never read
    }

    cudaGridDependencySynchronize();             // HW wait for proj

    // ---- load Pa: 1152 float4 coalesced, 4 per thread ----
    #pragma unroll
    for (int k = 0; k < 4; k++)
        reinterpret_cast<float4*>(sPc)[tid + k * 288] = __ldg(&g_Pa4[tid + k * 288]);
    __syncthreads();

    // ---- redundant in-block scan: threads 0..255, 2 tokens each ----
    float a0[NLAB], pr[NLAB], inc[NLAB];
    if (tid < 256) {
        const int t0 = tid * 2;
        #pragma unroll
        for (int j = 0; j < NLAB; j++) {
            a0[j] = sPc[t0 * NLAB + j];
            pr[j] = a0[j] + sPc[(t0 + 1) * NLAB + j];
        }
        #pragma unroll
        for (int j = 0; j < NLAB; j++) {
            float x = pr[j];
            #pragma unroll
            for (int o = 1; o < 32; o <<= 1) {
                const float y = __shfl_up_sync(0xffffffffu, x, o);
                if (lane >= o) x += y;
            }
            inc[j] = x;
        }
        if (lane == 31) {
            #pragma unroll
            for (int j = 0; j < NLAB; j++) tot[warp][j] = inc[j];
        }
    }
    __syncthreads();
    if (tid < NLAB) {
        float r = 0.f;
        #pragma unroll
        for (int w = 0; w < 8; w++) { carry[w][tid] = r; r += tot[w][tid]; }
    }
    __syncthreads();
    if (tid < 256) {
        const int t0 = tid * 2;
        #pragma unroll
        for (int j = 0; j < NLAB; j++) {
            const float pc0 = inc[j] - pr[j] + carry[warp][j];  // Pc[t0]
            sPc[t0 * NLAB + j]       = pc0;
            sPc[(t0 + 1) * NLAB + j] = pc0 + a0[j];             // Pc[t0+1]
        }
    }
    __syncthreads();

    // ---- assemble: 2 elements/thread, coalesced stores ----
    const float psA = __ldg(&g_Ps[sA * NLAB + l]);
    const float peA = __ldg(&g_Pe[eA * NLAB + l]);
    const float psB = __ldg(&g_Ps[sB * NLAB + l]);
    const float peB = __ldg(&g_Pe[eB * NLAB + l]);
    const float2 fwA = sWb[wA * NLAB + l];
    const float2 fwB = sWb[wB * NLAB + l];
    const float dA = sPc[eA * NLAB + l] - sPc[sA * NLAB + l];
    const float dB = sPc[eB * NLAB + l] - sPc[sB * NLAB + l];

    const int m = blockIdx.x * 288 + tid;
    out[m]                      = psA + peA + dA * fwA.y + fwA.x;
    out[m + NSPANS * NLAB / 2]  = psB + peB + dB * fwB.y + fwB.x;
}

// ---------------------------------------------------------------------------
extern "C" void kernel_launch(void* const* d_in, const int* in_sizes, int n_in,
                              void* d_out, int out_size) {
    const float* seq = (const float*)d_in[0];   // [1,512,768]
    const int*   st  = (const int*)  d_in[1];   // [32768]
    const int*   en  = (const int*)  d_in[2];   // [32768]
    const int*   wd  = (const int*)  d_in[3];   // [32768]
    const float* wt  = (const float*)d_in[4];   // [17,50]
    const float* W   = (const float*)d_in[5];   // [9,2354]
    const float* b   = (const float*)d_in[6];   // [9]
    float* out = (float*)d_out;                 // [32768,9]

    proj_kernel<<<SEQ_LEN / 2, 576>>>(seq, W);

    cudaLaunchAttribute at[1];
    at[0].id = cudaLaunchAttributeProgrammaticStreamSerialization;
    at[0].val.programmaticStreamSerializationAllowed = 1;

    cudaLaunchConfig_t cfg = {};
    cfg.gridDim  = dim3(NSPANS / 64, 1, 1);     // 512 blocks
    cfg.blockDim = dim3(288, 1, 1);
    cfg.stream   = 0;
    cfg.attrs    = at;
    cfg.numAttrs = 1;
    cudaLaunchKernelEx(&cfg, assemble_kernel, st, en, wd, wt, W, b, out);
}

// round 16
// speedup vs baseline: 1.1358x; 1.0172x over previous
#include <cuda_runtime.h>

// Problem constants (fixed by the reference)
#define SEQ_LEN   512
#define EMB       768
#define NLAB      9
#define FEAT      2354            // 3*768 + 50
#define WDIM      50
#define MAXW      16
#define NSPANS    32768
#define HALFK     384             // EMB/2 per k-half warp-group

// Packed fp32x2 FMA (Blackwell FFMA2 — only reachable via PTX f32x2)
#define FMA_F32X2(d, a, b, c) \
    asm("fma.rn.f32x2 %0, %1, %2, %3;" : "=l"(d) : "l"(a), "l"(b), "l"(c))

// Tables (allocation-free rule: __device__ globals)
__device__ float  g_Ps[SEQ_LEN * NLAB];      // start-token projection
__device__ float  g_Pe[SEQ_LEN * NLAB];      // end-token projection
__device__ float4 g_Pa4[SEQ_LEN * NLAB / 4]; // avg-slice projection (16B-aligned)

// ---------------------------------------------------------------------------
// K1: token projection — R13's 56-reg scalar body, but with NO smem staging:
// seq read directly via __ldg u64 (9 warps share lines -> L1 broadcast).
// Both pre-mainloop __syncthreads are gone; warps start FMA work at launch.
// 256 blocks x 576 threads, 2 tokens/block, k-split across 2 warp-groups.
// ---------------------------------------------------------------------------
__global__ void __launch_bounds__(576, 2)
proj_kernel(const float* __restrict__ seq, const float* __restrict__ W) {
    __shared__ float spart[2][2 * 27];                // [token][kh*27+j]

    const int tid  = threadIdx.x;
    const int warp = tid >> 5;          // 0..17
    const int lane = tid & 31;
    const int t0   = blockIdx.x * 2;

    const int kh    = warp / 9;         // 0..1  k-half
    const int jg    = warp - 9 * kh;    // 0..8  dot-group
    const int kbase = kh * HALFK;

    const float* s0p = seq + (size_t)t0 * EMB + kbase;    // 8B-aligned
    const float* s1p = s0p + EMB;

    const float* wbase[3];
    #pragma unroll
    for (int i = 0; i < 3; i++) {
        const int j = jg * 3 + i;
        const int l = j % 9, sl = j / 9;
        wbase[i] = W + (size_t)l * FEAT + sl * EMB + kbase;   // 8B-aligned
    }

    unsigned long long a0[3] = {0ull, 0ull, 0ull};
    unsigned long long a1[3] = {0ull, 0ull, 0ull};

    #pragma unroll
    for (int it = 0; it < 6; it++) {
        const int k = it * 64 + lane * 2;
        const unsigned long long s0 =
            __ldg(reinterpret_cast<const unsigned long long*>(s0p + k));
        const unsigned long long s1 =
            __ldg(reinterpret_cast<const unsigned long long*>(s1p + k));
        #pragma unroll
        for (int i = 0; i < 3; i++) {
            const unsigned long long wv =
                __ldg(reinterpret_cast<const unsigned long long*>(wbase[i] + k));
            FMA_F32X2(a0[i], s0, wv, a0[i]);
            FMA_F32X2(a1[i], s1, wv, a1[i]);
        }
    }

    // Collapse f32x2 -> f32, shfl-reduce across lanes.
    float r0[3], r1[3];
    #pragma unroll
    for (int i = 0; i < 3; i++) {
        const float2 f0 = *reinterpret_cast<float2*>(&a0[i]);
        const float2 f1 = *reinterpret_cast<float2*>(&a1[i]);
        r0[i] = f0.x + f0.y;
        r1[i] = f1.x + f1.y;
    }
    #pragma unroll
    for (int i = 0; i < 3; i++) {
        #pragma unroll
        for (int o = 16; o > 0; o >>= 1) {
            r0[i] += __shfl_down_sync(0xffffffffu, r0[i], o);
            r1[i] += __shfl_down_sync(0xffffffffu, r1[i], o);
        }
    }
    if (lane == 0) {
        #pragma unroll
        for (int i = 0; i < 3; i++) {
            spart[0][kh * 27 + jg * 3 + i] = r0[i];
            spart[1][kh * 27 + jg * 3 + i] = r1[i];
        }
    }
    __syncthreads();

    // Combine the two k-halves; 54 threads write finals.
    if (tid < 54) {
        const int t = tid / 27;             // 0..1
        const int j = tid - t * 27;         // 0..26
        const float v = spart[t][j] + spart[t][27 + j];
        const int sl = j / 9, l = j - sl * 9;
        const int tok = t0 + t;
        if (sl == 0)      g_Ps[tok * NLAB + l] = v;
        else if (sl == 1) g_Pe[tok * NLAB + l] = v;
        else              reinterpret_cast<float*>(g_Pa4)[tok * NLAB + l] = v;
    }
    __syncthreads();
    cudaTriggerProgrammaticLaunchCompletion();   // release K2 at last-store time
}

// ---------------------------------------------------------------------------
// K2 (PDL): scan + assemble fused (R15's winning kernel, unchanged).
// 512 blocks x 288 thr. Prologue overlaps proj; gridsync; coalesced Pa load;
// redundant in-block 9-label scan -> Pc in smem; assemble 2 elems/thread.
// ---------------------------------------------------------------------------
__global__ void __launch_bounds__(288)
assemble_kernel(const int* __restrict__ st,
                const int* __restrict__ en,
                const int* __restrict__ wd,
                const float* __restrict__ wt,
                const float* __restrict__ W,
                const float* __restrict__ b,
                float* __restrict__ out) {
    __shared__ __align__(16) float sPc[SEQ_LEN * NLAB];  // Pa, scanned in place
    __shared__ float2 sWb[(MAXW + 1) * NLAB];
    __shared__ float tot[8][NLAB];
    __shared__ float carry[8][NLAB];

    const int tid  = threadIdx.x;
    const int lane = tid & 31;
    const int warp = tid >> 5;
    const int sp_l = tid / NLAB;                 // 0..31
    const int l    = tid - sp_l * NLAB;          // 0..8
    const int spanA = blockIdx.x * 32 + sp_l;
    const int spanB = spanA + NSPANS / 2;

    // ---- prologue: inputs only (overlaps proj via PDL) ----
    const int sA = __ldg(st + spanA);
    const int eA = __ldg(en + spanA);
    const int wA = __ldg(wd + spanA);
    const int sB = __ldg(st + spanB);
    const int eB = __ldg(en + spanB);
    const int wB = __ldg(wd + spanB);

    if (tid < (MAXW + 1) * NLAB) {
        const int w = tid / NLAB;
        const int ll = tid - w * NLAB;
        const float* wrow = W + (size_t)ll * FEAT + 3 * EMB;
        float a = __ldg(b + ll);
        #pragma unroll
        for (int k = 0; k < WDIM; k++)
            a += __ldg(wt + w * WDIM + k) * __ldg(wrow + k);
        sWb[tid] = make_float2(a, 1.0f / (float)w);   // w=0 never read
    }

    cudaGridDependencySynchronize();             // HW wait for proj

    // ---- load Pa: 1152 float4 coalesced, 4 per thread ----
    #pragma unroll
    for (int k = 0; k < 4; k++)
        reinterpret_cast<float4*>(sPc)[tid + k * 288] = __ldg(&g_Pa4[tid + k * 288]);
    __syncthreads();

    // ---- redundant in-block scan: threads 0..255, 2 tokens each ----
    float a0[NLAB], pr[NLAB], inc[NLAB];
    if (tid < 256) {
        const int t0 = tid * 2;
        #pragma unroll
        for (int j = 0; j < NLAB; j++) {
            a0[j] = sPc[t0 * NLAB + j];
            pr[j] = a0[j] + sPc[(t0 + 1) * NLAB + j];
        }
        #pragma unroll
        for (int j = 0; j < NLAB; j++) {
            float x = pr[j];
            #pragma unroll
            for (int o = 1; o < 32; o <<= 1) {
                const float y = __shfl_up_sync(0xffffffffu, x, o);
                if (lane >= o) x += y;
            }
            inc[j] = x;
        }
        if (lane == 31) {
            #pragma unroll
            for (int j = 0; j < NLAB; j++) tot[warp][j] = inc[j];
        }
    }
    __syncthreads();
    if (tid < NLAB) {
        float r = 0.f;
        #pragma unroll
        for (int w = 0; w < 8; w++) { carry[w][tid] = r; r += tot[w][tid]; }
    }
    __syncthreads();
    if (tid < 256) {
        const int t0 = tid * 2;
        #pragma unroll
        for (int j = 0; j < NLAB; j++) {
            const float pc0 = inc[j] - pr[j] + carry[warp][j];  // Pc[t0]
            sPc[t0 * NLAB + j]       = pc0;
            sPc[(t0 + 1) * NLAB + j] = pc0 + a0[j];             // Pc[t0+1]
        }
    }
    __syncthreads();

    // ---- assemble: 2 elements/thread, coalesced stores ----
    const float psA = __ldg(&g_Ps[sA * NLAB + l]);
    const float peA = __ldg(&g_Pe[eA * NLAB + l]);
    const float psB = __ldg(&g_Ps[sB * NLAB + l]);
    const float peB = __ldg(&g_Pe[eB * NLAB + l]);
    const float2 fwA = sWb[wA * NLAB + l];
    const float2 fwB = sWb[wB * NLAB + l];
    const float dA = sPc[eA * NLAB + l] - sPc[sA * NLAB + l];
    const float dB = sPc[eB * NLAB + l] - sPc[sB * NLAB + l];

    const int m = blockIdx.x * 288 + tid;
    out[m]                      = psA + peA + dA * fwA.y + fwA.x;
    out[m + NSPANS * NLAB / 2]  = psB + peB + dB * fwB.y + fwB.x;
}

// ---------------------------------------------------------------------------
extern "C" void kernel_launch(void* const* d_in, const int* in_sizes, int n_in,
                              void* d_out, int out_size) {
    const float* seq = (const float*)d_in[0];   // [1,512,768]
    const int*   st  = (const int*)  d_in[1];   // [32768]
    const int*   en  = (const int*)  d_in[2];   // [32768]
    const int*   wd  = (const int*)  d_in[3];   // [32768]
    const float* wt  = (const float*)d_in[4];   // [17,50]
    const float* W   = (const float*)d_in[5];   // [9,2354]
    const float* b   = (const float*)d_in[6];   // [9]
    float* out = (float*)d_out;                 // [32768,9]

    proj_kernel<<<SEQ_LEN / 2, 576>>>(seq, W);

    cudaLaunchAttribute at[1];
    at[0].id = cudaLaunchAttributeProgrammaticStreamSerialization;
    at[0].val.programmaticStreamSerializationAllowed = 1;

    cudaLaunchConfig_t cfg = {};
    cfg.gridDim  = dim3(NSPANS / 64, 1, 1);     // 512 blocks
    cfg.blockDim = dim3(288, 1, 1);
    cfg.stream   = 0;
    cfg.attrs    = at;
    cfg.numAttrs = 1;
    cudaLaunchKernelEx(&cfg, assemble_kernel, st, en, wd, wt, W, b, out);
}

// round 17
// speedup vs baseline: 1.3175x; 1.1600x over previous
#include <cuda_runtime.h>

// Problem constants (fixed by the reference)
#define SEQ_LEN   512
#define EMB       768
#define NLAB      9
#define FEAT      2354            // 3*768 + 50
#define WDIM      50
#define MAXW      16
#define NSPANS    32768
#define HALFK     384             // EMB/2 per k-half warp-group
#define QSPAN     (NSPANS / 4)    // 8192 spans per quarter
#define QOUT      (NSPANS * NLAB / 4)

// Packed fp32x2 FMA (Blackwell FFMA2 — only reachable via PTX f32x2)
#define FMA_F32X2(d, a, b, c) \
    asm("fma.rn.f32x2 %0, %1, %2, %3;" : "=l"(d) : "l"(a), "l"(b), "l"(c))

// Tables (allocation-free rule: __device__ globals)
__device__ float  g_Ps[SEQ_LEN * NLAB];      // start-token projection
__device__ float  g_Pe[SEQ_LEN * NLAB];      // end-token projection
__device__ float4 g_Pa4[SEQ_LEN * NLAB / 4]; // avg-slice projection (16B-aligned)

// ---------------------------------------------------------------------------
// K1: token projection — R16's measured-best body, byte-identical (56-reg
// scalar accumulators, no smem staging, direct __ldg u64 seq reads).
// 256 blocks x 576 threads, 2 tokens/block, k-split across 2 warp-groups.
// ---------------------------------------------------------------------------
__global__ void __launch_bounds__(576, 2)
proj_kernel(const float* __restrict__ seq, const float* __restrict__ W) {
    __shared__ float spart[2][2 * 27];                // [token][kh*27+j]

    const int tid  = threadIdx.x;
    const int warp = tid >> 5;          // 0..17
    const int lane = tid & 31;
    const int t0   = blockIdx.x * 2;

    const int kh    = warp / 9;         // 0..1  k-half
    const int jg    = warp - 9 * kh;    // 0..8  dot-group
    const int kbase = kh * HALFK;

    const float* s0p = seq + (size_t)t0 * EMB + kbase;    // 8B-aligned
    const float* s1p = s0p + EMB;

    const float* wbase[3];
    #pragma unroll
    for (int i = 0; i < 3; i++) {
        const int j = jg * 3 + i;
        const int l = j % 9, sl = j / 9;
        wbase[i] = W + (size_t)l * FEAT + sl * EMB + kbase;   // 8B-aligned
    }

    unsigned long long a0[3] = {0ull, 0ull, 0ull};
    unsigned long long a1[3] = {0ull, 0ull, 0ull};

    #pragma unroll
    for (int it = 0; it < 6; it++) {
        const int k = it * 64 + lane * 2;
        const unsigned long long s0 =
            __ldg(reinterpret_cast<const unsigned long long*>(s0p + k));
        const unsigned long long s1 =
            __ldg(reinterpret_cast<const unsigned long long*>(s1p + k));
        #pragma unroll
        for (int i = 0; i < 3; i++) {
            const unsigned long long wv =
                __ldg(reinterpret_cast<const unsigned long long*>(wbase[i] + k));
            FMA_F32X2(a0[i], s0, wv, a0[i]);
            FMA_F32X2(a1[i], s1, wv, a1[i]);
        }
    }

    // Collapse f32x2 -> f32, shfl-reduce across lanes.
    float r0[3], r1[3];
    #pragma unroll
    for (int i = 0; i < 3; i++) {
        const float2 f0 = *reinterpret_cast<float2*>(&a0[i]);
        const float2 f1 = *reinterpret_cast<float2*>(&a1[i]);
        r0[i] = f0.x + f0.y;
        r1[i] = f1.x + f1.y;
    }
    #pragma unroll
    for (int i = 0; i < 3; i++) {
        #pragma unroll
        for (int o = 16; o > 0; o >>= 1) {
            r0[i] += __shfl_down_sync(0xffffffffu, r0[i], o);
            r1[i] += __shfl_down_sync(0xffffffffu, r1[i], o);
        }
    }
    if (lane == 0) {
        #pragma unroll
        for (int i = 0; i < 3; i++) {
            spart[0][kh * 27 + jg * 3 + i] = r0[i];
            spart[1][kh * 27 + jg * 3 + i] = r1[i];
        }
    }
    __syncthreads();

    // Combine the two k-halves; 54 threads write finals.
    if (tid < 54) {
        const int t = tid / 27;             // 0..1
        const int j = tid - t * 27;         // 0..26
        const float v = spart[t][j] + spart[t][27 + j];
        const int sl = j / 9, l = j - sl * 9;
        const int tok = t0 + t;
        if (sl == 0)      g_Ps[tok * NLAB + l] = v;
        else if (sl == 1) g_Pe[tok * NLAB + l] = v;
        else              reinterpret_cast<float*>(g_Pa4)[tok * NLAB + l] = v;
    }
    __syncthreads();
    cudaTriggerProgrammaticLaunchCompletion();   // release K2 at last-store time
}

// ---------------------------------------------------------------------------
// K2 (PDL): scan + assemble fused, 256 blocks x 288 thr, 4 spans/thread.
// Redundant Pa traffic + scan count halved vs the 512-block version; all 12
// idx loads batched in the PDL prologue; 4-way MLP on post-sync gathers.
// ---------------------------------------------------------------------------
__global__ void __launch_bounds__(288)
assemble_kernel(const int* __restrict__ st,
                const int* __restrict__ en,
                const int* __restrict__ wd,
                const float* __restrict__ wt,
                const float* __restrict__ W,
                const float* __restrict__ b,
                float* __restrict__ out) {
    __shared__ __align__(16) float sPc[SEQ_LEN * NLAB];  // Pa, scanned in place
    __shared__ float2 sWb[(MAXW + 1) * NLAB];
    __shared__ float tot[8][NLAB];
    __shared__ float carry[8][NLAB];

    const int tid  = threadIdx.x;
    const int lane = tid & 31;
    const int warp = tid >> 5;
    const int sp_l = tid / NLAB;                 // 0..31
    const int l    = tid - sp_l * NLAB;          // 0..8
    const int spanA = blockIdx.x * 32 + sp_l;
    const int spanB = spanA + QSPAN;
    const int spanC = spanA + 2 * QSPAN;
    const int spanD = spanA + 3 * QSPAN;

    // ---- prologue: inputs only (overlaps proj via PDL) ----
    const int sA = __ldg(st + spanA), eA = __ldg(en + spanA), wA = __ldg(wd + spanA);
    const int sB = __ldg(st + spanB), eB = __ldg(en + spanB), wB = __ldg(wd + spanB);
    const int sC = __ldg(st + spanC), eC = __ldg(en + spanC), wC = __ldg(wd + spanC);
    const int sD = __ldg(st + spanD), eD = __ldg(en + spanD), wD = __ldg(wd + spanD);

    if (tid < (MAXW + 1) * NLAB) {
        const int w = tid / NLAB;
        const int ll = tid - w * NLAB;
        const float* wrow = W + (size_t)ll * FEAT + 3 * EMB;
        float a = __ldg(b + ll);
        #pragma unroll
        for (int k = 0; k < WDIM; k++)
            a += __ldg(wt + w * WDIM + k) * __ldg(wrow + k);
        sWb[tid] = make_float2(a, 1.0f / (float)w);   // w=0 never read
    }

    cudaGridDependencySynchronize();             // HW wait for proj

    // ---- load Pa: 1152 float4 coalesced, 4 per thread ----
    #pragma unroll
    for (int k = 0; k < 4; k++)
        reinterpret_cast<float4*>(sPc)[tid + k * 288] = __ldg(&g_Pa4[tid + k * 288]);
    __syncthreads();

    // ---- redundant in-block scan: threads 0..255, 2 tokens each ----
    float a0[NLAB], pr[NLAB], inc[NLAB];
    if (tid < 256) {
        const int t0 = tid * 2;
        #pragma unroll
        for (int j = 0; j < NLAB; j++) {
            a0[j] = sPc[t0 * NLAB + j];
            pr[j] = a0[j] + sPc[(t0 + 1) * NLAB + j];
        }
        #pragma unroll
        for (int j = 0; j < NLAB; j++) {
            float x = pr[j];
            #pragma unroll
            for (int o = 1; o < 32; o <<= 1) {
                const float y = __shfl_up_sync(0xffffffffu, x, o);
                if (lane >= o) x += y;
            }
            inc[j] = x;
        }
        if (lane == 31) {
            #pragma unroll
            for (int j = 0; j < NLAB; j++) tot[warp][j] = inc[j];
        }
    }
    __syncthreads();
    if (tid < NLAB) {
        float r = 0.f;
        #pragma unroll
        for (int w = 0; w < 8; w++) { carry[w][tid] = r; r += tot[w][tid]; }
    }
    __syncthreads();
    if (tid < 256) {
        const int t0 = tid * 2;
        #pragma unroll
        for (int j = 0; j < NLAB; j++) {
            const float pc0 = inc[j] - pr[j] + carry[warp][j];  // Pc[t0]
            sPc[t0 * NLAB + j]       = pc0;
            sPc[(t0 + 1) * NLAB + j] = pc0 + a0[j];             // Pc[t0+1]
        }
    }
    __syncthreads();

    // ---- assemble: 4 elements/thread, gathers batched, coalesced stores ----
    const float psA = __ldg(&g_Ps[sA * NLAB + l]);
    const float peA = __ldg(&g_Pe[eA * NLAB + l]);
    const float psB = __ldg(&g_Ps[sB * NLAB + l]);
    const float peB = __ldg(&g_Pe[eB * NLAB + l]);
    const float psC = __ldg(&g_Ps[sC * NLAB + l]);
    const float peC = __ldg(&g_Pe[eC * NLAB + l]);
    const float psD = __ldg(&g_Ps[sD * NLAB + l]);
    const float peD = __ldg(&g_Pe[eD * NLAB + l]);
    const float2 fwA = sWb[wA * NLAB + l];
    const float2 fwB = sWb[wB * NLAB + l];
    const float2 fwC = sWb[wC * NLAB + l];
    const float2 fwD = sWb[wD * NLAB + l];
    const float dA = sPc[eA * NLAB + l] - sPc[sA * NLAB + l];
    const float dB = sPc[eB * NLAB + l] - sPc[sB * NLAB + l];
    const float dC = sPc[eC * NLAB + l] - sPc[sC * NLAB + l];
    const float dD = sPc[eD * NLAB + l] - sPc[sD * NLAB + l];

    const int m = blockIdx.x * 288 + tid;
    out[m]            = psA + peA + dA * fwA.y + fwA.x;
    out[m + QOUT]     = psB + peB + dB * fwB.y + fwB.x;
    out[m + 2 * QOUT] = psC + peC + dC * fwC.y + fwC.x;
    out[m + 3 * QOUT] = psD + peD + dD * fwD.y + fwD.x;
}

// ---------------------------------------------------------------------------
extern "C" void kernel_launch(void* const* d_in, const int* in_sizes, int n_in,
                              void* d_out, int out_size) {
    const float* seq = (const float*)d_in[0];   // [1,512,768]
    const int*   st  = (const int*)  d_in[1];   // [32768]
    const int*   en  = (const int*)  d_in[2];   // [32768]
    const int*   wd  = (const int*)  d_in[3];   // [32768]
    const float* wt  = (const float*)d_in[4];   // [17,50]
    const float* W   = (const float*)d_in[5];   // [9,2354]
    const float* b   = (const float*)d_in[6];   // [9]
    float* out = (float*)d_out;                 // [32768,9]

    proj_kernel<<<SEQ_LEN / 2, 576>>>(seq, W);

    cudaLaunchAttribute at[1];
    at[0].id = cudaLaunchAttributeProgrammaticStreamSerialization;
    at[0].val.programmaticStreamSerializationAllowed = 1;

    cudaLaunchConfig_t cfg = {};
    cfg.gridDim  = dim3(QSPAN / 32, 1, 1);      // 256 blocks
    cfg.blockDim = dim3(288, 1, 1);
    cfg.stream   = 0;
    cfg.attrs    = at;
    cfg.numAttrs = 1;
    cudaLaunchKernelEx(&cfg, assemble_kernel, st, en, wd, wt, W, b, out);
}